// round 1
// baseline (speedup 1.0000x reference)
#include <cuda_runtime.h>
#include <cmath>

#define NLEVELS 16
#define MAXRES 2048
#define PLANE_ELEMS (MAXRES * MAXRES)   // float2 elements per plane
#define LUT_CAP 7424                     // sum(res) = 7388, padded
#define TPB 256

struct Cfg {
    int   lo[NLEVELS];
    int   res[NLEVELS];
    float rm1[NLEVELS];
    int   total;
};

// Device-global scratch for the c_ori LUT (allowed: no allocation).
__device__ unsigned g_lut[LUT_CAP];

// Bit-exact replication of: (c / res * 2047).astype(int32) in fp32 rn + truncation.
__global__ void build_lut_kernel(Cfg cfg) {
    int l   = blockIdx.x;
    int res = cfg.res[l];
    int lo  = cfg.lo[l];
    float rf = (float)res;
    for (int c = threadIdx.x; c < res; c += blockDim.x) {
        float q0 = __fmul_rn(__fdiv_rn((float)c,       rf), 2047.0f);
        float q1 = __fmul_rn(__fdiv_rn((float)(c + 1), rf), 2047.0f);
        unsigned a = (unsigned)(int)q0;   // trunc toward zero, values >= 0
        unsigned b = (unsigned)(int)q1;
        g_lut[lo + c] = a | (b << 16);
    }
}

__device__ __forceinline__ float2 plane_eval(float ax, float ay, float rm1,
                                             const unsigned* lutl,
                                             const float2* __restrict__ pl) {
    float posx = fmaf(ax, rm1, 0.5f);
    float posy = fmaf(ay, rm1, 0.5f);
    float gx = floorf(posx);
    float gy = floorf(posy);
    float fx = posx - gx;
    float fy = posy - gy;
    int ix = (int)gx;
    int iy = (int)gy;
    unsigned vx = lutl[ix];                 // packed {c_ori(ix), c_ori(ix+1)}
    unsigned vy = lutl[iy];
    int x0 = (int)(vx & 0xffffu);
    int x1 = (int)(vx >> 16);
    int y0 = ((int)(vy & 0xffffu)) << 11;   // * MAXRES
    int y1 = ((int)(vy >> 16))     << 11;
    float2 t00 = pl[x0 + y0];
    float2 t01 = pl[x1 + y0];
    float2 t10 = pl[x0 + y1];
    float2 t11 = pl[x1 + y1];
    // Bilinear via lerp (mathematically identical to the 4-weight sum; fp
    // differences are ~1 ulp and smooth — index path above is the exact part).
    float m0x = fmaf(fx, t01.x - t00.x, t00.x);
    float m0y = fmaf(fx, t01.y - t00.y, t00.y);
    float m1x = fmaf(fx, t11.x - t10.x, t10.x);
    float m1y = fmaf(fx, t11.y - t10.y, t10.y);
    float2 r;
    r.x = fmaf(fy, m1x - m0x, m0x);
    r.y = fmaf(fy, m1y - m0y, m0y);
    return r;
}

__global__ void __launch_bounds__(TPB, 3)
triplane_kernel(const float* __restrict__ positions,
                const float* __restrict__ table,
                float* __restrict__ out,
                Cfg cfg, int B) {
    extern __shared__ unsigned smem[];
    unsigned* lut = smem;                         // LUT_CAP u32
    float*    so  = (float*)(smem + LUT_CAP);     // TPB * 33 floats (padded)

    int tid = threadIdx.x;
    int b   = blockIdx.x * TPB + tid;

    // Cooperative LUT copy (coalesced, 29.5 KB)
    for (int i = tid; i < cfg.total; i += TPB)
        lut[i] = g_lut[i];

    float px = 0.f, py = 0.f, pz = 0.f;
    if (b < B) {
        px = positions[3 * b + 0];
        py = positions[3 * b + 1];
        pz = positions[3 * b + 2];
    }
    __syncthreads();

    const float2* pl0 = (const float2*)table;
    const float2* pl1 = pl0 + PLANE_ELEMS;
    const float2* pl2 = pl1 + PLANE_ELEMS;

    if (b < B) {
        float* row = so + tid * 33;
        #pragma unroll 4
        for (int l = 0; l < NLEVELS; ++l) {
            float rm1 = cfg.rm1[l];
            const unsigned* lutl = lut + cfg.lo[l];
            float2 q0 = plane_eval(px, py, rm1, lutl, pl0);
            float2 q1 = plane_eval(py, pz, rm1, lutl, pl1);
            float2 q2 = plane_eval(pz, px, rm1, lutl, pl2);
            row[l]      = q0.x * q1.x * q2.x;   // out[b, 0*16 + l]
            row[16 + l] = q0.y * q1.y * q2.y;   // out[b, 1*16 + l]
        }
    }
    __syncthreads();

    // Coalesced flush: this block's outputs are contiguous in gmem.
    int base  = blockIdx.x * (TPB * 32);
    int limit = B * 32 - base;
    if (limit > TPB * 32) limit = TPB * 32;
    for (int k = tid; k < limit; k += TPB)
        out[base + k] = so[(k >> 5) * 33 + (k & 31)];
}

extern "C" void kernel_launch(void* const* d_in, const int* in_sizes, int n_in,
                              void* d_out, int out_size) {
    const float* positions = (const float*)d_in[0];
    const float* table     = (const float*)d_in[1];
    float*       out       = (float*)d_out;
    int B = in_sizes[0] / 3;

    // Replicate the Python host math (same glibc log/exp in this container).
    Cfg cfg;
    double LOG_B = log(2048.0 / 16.0) / 15.0;
    int off = 0;
    for (int l = 0; l < NLEVELS; ++l) {
        double scale = 16.0 * exp((double)l * LOG_B) - 1.0;
        int res = (int)ceil(scale) + 1;
        cfg.res[l] = res;
        cfg.rm1[l] = (float)(res - 1);
        cfg.lo[l]  = off;
        off += res;
    }
    cfg.total = off;   // 7388 <= LUT_CAP

    size_t shmem = (size_t)LUT_CAP * 4 + (size_t)TPB * 33 * 4;  // 63488 B
    cudaFuncSetAttribute(triplane_kernel,
                         cudaFuncAttributeMaxDynamicSharedMemorySize, (int)shmem);

    build_lut_kernel<<<NLEVELS, TPB>>>(cfg);
    int grid = (B + TPB - 1) / TPB;
    triplane_kernel<<<grid, TPB, shmem>>>(positions, table, out, cfg, B);
}